// round 4
// baseline (speedup 1.0000x reference)
#include <cuda_runtime.h>

#define EMBED 128
#define ATTR 25
#define REM 28
#define NLEVEL 50
#define NTFX 12           // 2*2*3 combined type/feature/exchange rows
#define NPAIR 20

// Main-kernel smem: 82 rows * 128 floats = 42 KB
#define F_TFX   (NLEVEL * EMBED)             // 6400
#define F_PAIR  (F_TFX + NTFX * EMBED)       // 7936
#define MAIN_SMEM_FLOATS (F_PAIR + NPAIR * EMBED)   // 10496
#define MAIN_SMEM_BYTES  (MAIN_SMEM_FLOATS * 4)     // 41984

// Table-kernel smem: W^T (16384) + 77 temp rows (9856)
#define TK_TEMP  16384
#define TK_SMEM_FLOATS (TK_TEMP + 77 * EMBED)
#define TK_SMEM_BYTES  (TK_SMEM_FLOATS * 4)          // 104960

// Precomputed projected tables (b folded into pair rows)
__device__ float g_L[NLEVEL * EMBED];
__device__ float g_TFX[NTFX * EMBED];
__device__ float g_PAIR[NPAIR * EMBED];

// One block: builds all three projected tables. ~2-3us.
__global__ void __launch_bounds__(1024, 1)
table_kernel(const float* __restrict__ level_tab,
             const float* __restrict__ type_tab,
             const float* __restrict__ feature_tab,
             const float* __restrict__ exchange_tab,
             const float* __restrict__ pair_tab,
             const float* __restrict__ W,
             const float* __restrict__ b)
{
    extern __shared__ float sm[];
    float* sWt  = sm;             // [128k + e] = W[e][k], conflict-free reads
    float* sTmp = sm + TK_TEMP;   // 77 projected rows

    for (int i = threadIdx.x; i < EMBED * EMBED; i += 1024) {
        int e = i >> 7, k = i & 127;
        sWt[k * EMBED + e] = W[i];
    }
    __syncthreads();

    // 77 projected rows: r<50 level, 50-51 type, 52-53 feature, 54-56 exchange, 57-76 pair(+b)
    for (int i = threadIdx.x; i < 77 * EMBED; i += 1024) {
        int r = i >> 7, e = i & 127;
        const float* tab; int off, dim; float s = 0.0f;
        if (r < 50)      { tab = level_tab    + r * ATTR;        off = 0;   dim = ATTR; }
        else if (r < 52) { tab = type_tab     + (r - 50) * ATTR; off = 25;  dim = ATTR; }
        else if (r < 54) { tab = feature_tab  + (r - 52) * ATTR; off = 50;  dim = ATTR; }
        else if (r < 57) { tab = exchange_tab + (r - 54) * ATTR; off = 75;  dim = ATTR; }
        else             { tab = pair_tab     + (r - 57) * REM;  off = 100; dim = REM; s = b[e]; }
        #pragma unroll 5
        for (int k = 0; k < dim; k++)
            s += tab[k] * sWt[(off + k) * EMBED + e];
        sTmp[r * EMBED + e] = s;
    }
    __syncthreads();

    for (int i = threadIdx.x; i < NLEVEL * EMBED; i += 1024) g_L[i] = sTmp[i];
    for (int i = threadIdx.x; i < NTFX * EMBED; i += 1024) {
        int c = i >> 7, e = i & 127;
        int x = c % 3, f = (c / 3) % 2, t = c / 6;    // c = (t*2+f)*3+x
        g_TFX[i] = sTmp[(50 + t) * EMBED + e]
                 + sTmp[(52 + f) * EMBED + e]
                 + sTmp[(54 + x) * EMBED + e];
    }
    for (int i = threadIdx.x; i < NPAIR * EMBED; i += 1024)
        g_PAIR[i] = sTmp[(57 * EMBED) + i];           // b already folded
}

// Streaming kernel: 3 blocks/SM x 512 threads = 48 warps/SM.
// Warp per row, 4 rows/iter, lane owns one float4 of the 128-wide output.
__global__ void __launch_bounds__(512, 3)
gather_sum_kernel(const int* __restrict__ level_idx,
                  const int* __restrict__ type_idx,
                  const int* __restrict__ feature_idx,
                  const int* __restrict__ exchange_idx,
                  const int* __restrict__ pair_idx,
                  float4* __restrict__ out, int n)
{
    extern __shared__ float sm[];
    {
        const float* gl = g_L; const float* gt = g_TFX; const float* gp = g_PAIR;
        for (int i = threadIdx.x; i < NLEVEL * EMBED; i += 512) sm[i] = gl[i];
        for (int i = threadIdx.x; i < NTFX * EMBED; i += 512)   sm[F_TFX + i] = gt[i];
        for (int i = threadIdx.x; i < NPAIR * EMBED; i += 512)  sm[F_PAIR + i] = gp[i];
    }
    __syncthreads();

    const float4* sL = reinterpret_cast<const float4*>(sm);
    const float4* sT = sL + (F_TFX / 4);    // +1600
    const float4* sQ = sL + (F_PAIR / 4);   // +1984

    const int lane   = threadIdx.x & 31;
    const int warp   = (blockIdx.x * 512 + threadIdx.x) >> 5;
    const int nwarps = (gridDim.x * 512) >> 5;

    int r = warp * 4;
    const int stride = nwarps * 4;

    for (; r + 3 < n; r += stride) {
        int4 L = *reinterpret_cast<const int4*>(level_idx + r);
        int4 T = *reinterpret_cast<const int4*>(type_idx + r);
        int4 F = *reinterpret_cast<const int4*>(feature_idx + r);
        int4 X = *reinterpret_cast<const int4*>(exchange_idx + r);
        int4 P = *reinterpret_cast<const int4*>(pair_idx + r);

        #pragma unroll
        for (int k = 0; k < 4; k++) {
            int l  = (k == 0) ? L.x : (k == 1) ? L.y : (k == 2) ? L.z : L.w;
            int t  = (k == 0) ? T.x : (k == 1) ? T.y : (k == 2) ? T.z : T.w;
            int f  = (k == 0) ? F.x : (k == 1) ? F.y : (k == 2) ? F.z : F.w;
            int x  = (k == 0) ? X.x : (k == 1) ? X.y : (k == 2) ? X.z : X.w;
            int p  = (k == 0) ? P.x : (k == 1) ? P.y : (k == 2) ? P.z : P.w;

            int c = (t * 2 + f) * 3 + x;
            float4 a = sL[l * 32 + lane];
            float4 u = sT[c * 32 + lane];
            float4 q = sQ[p * 32 + lane];
            float4 s;
            s.x = a.x + u.x + q.x;
            s.y = a.y + u.y + q.y;
            s.z = a.z + u.z + q.z;
            s.w = a.w + u.w + q.w;
            __stcs(out + (size_t)(r + k) * 32 + lane, s);
        }
    }
    for (; r < n; r++) {   // tail
        int c = (type_idx[r] * 2 + feature_idx[r]) * 3 + exchange_idx[r];
        float4 a = sL[level_idx[r] * 32 + lane];
        float4 u = sT[c * 32 + lane];
        float4 q = sQ[pair_idx[r] * 32 + lane];
        float4 s;
        s.x = a.x + u.x + q.x;
        s.y = a.y + u.y + q.y;
        s.z = a.z + u.z + q.z;
        s.w = a.w + u.w + q.w;
        out[(size_t)r * 32 + lane] = s;
    }
}

extern "C" void kernel_launch(void* const* d_in, const int* in_sizes, int n_in,
                              void* d_out, int out_size) {
    const float* level_tab    = (const float*)d_in[0];
    const float* type_tab     = (const float*)d_in[1];
    const float* feature_tab  = (const float*)d_in[2];
    const float* exchange_tab = (const float*)d_in[3];
    const float* pair_tab     = (const float*)d_in[4];
    const float* W            = (const float*)d_in[5];
    const float* b            = (const float*)d_in[6];
    const int* level_idx      = (const int*)d_in[7];
    const int* type_idx       = (const int*)d_in[8];
    const int* feature_idx    = (const int*)d_in[9];
    const int* exchange_idx   = (const int*)d_in[10];
    const int* pair_idx       = (const int*)d_in[11];

    int n = in_sizes[7];   // N rows

    int sm_count = 148;
    cudaDeviceGetAttribute(&sm_count, cudaDevAttrMultiProcessorCount, 0);

    cudaFuncSetAttribute(table_kernel,
                         cudaFuncAttributeMaxDynamicSharedMemorySize, TK_SMEM_BYTES);
    cudaFuncSetAttribute(gather_sum_kernel,
                         cudaFuncAttributeMaxDynamicSharedMemorySize, MAIN_SMEM_BYTES);

    table_kernel<<<1, 1024, TK_SMEM_BYTES>>>(level_tab, type_tab, feature_tab,
                                             exchange_tab, pair_tab, W, b);

    // 3 blocks/SM x 512 threads = 48 warps/SM, one resident wave
    gather_sum_kernel<<<3 * sm_count, 512, MAIN_SMEM_BYTES>>>(
        level_idx, type_idx, feature_idx, exchange_idx, pair_idx,
        (float4*)d_out, n);
}

// round 5
// speedup vs baseline: 1.0800x; 1.0800x over previous
#include <cuda_runtime.h>

#define EMBED 128
#define ATTR 25
#define REM 28
#define NLEVEL 50
#define NPROJ 77          // 50 level + 2 type + 2 feature + 3 exchange + 20 pair
#define NTEMP 27
#define NCOMB 240         // 2*2*3*20 combined rows

// smem layout (floats):
//   [0, 6400)      : 50 level projected rows
//   [6400, 9856)   : 27 temp projected rows
//   [9856, 40576)  : 240 combined rows (first 16384 double as W^T during phase A)
#define F_TEMP  (NLEVEL * EMBED)             // 6400
#define F_COMB  (F_TEMP + NTEMP * EMBED)     // 9856
#define SMEM_FLOATS (F_COMB + NCOMB * EMBED) // 40576
#define SMEM_BYTES  (SMEM_FLOATS * 4)        // 162304

__global__ void __launch_bounds__(1024, 1)
fused_embed_kernel(const float* __restrict__ level_tab,
                   const float* __restrict__ type_tab,
                   const float* __restrict__ feature_tab,
                   const float* __restrict__ exchange_tab,
                   const float* __restrict__ pair_tab,
                   const float* __restrict__ W,
                   const float* __restrict__ b,
                   const int* __restrict__ level_idx,
                   const int* __restrict__ type_idx,
                   const int* __restrict__ feature_idx,
                   const int* __restrict__ exchange_idx,
                   const int* __restrict__ pair_idx,
                   float4* __restrict__ out, int n)
{
    extern __shared__ float sm[];

    // ---- Phase 0: W transposed into (future) combined region: conflict-free phase-A reads.
    float* sWt = sm + F_COMB;
    for (int i = threadIdx.x; i < EMBED * EMBED; i += 1024) {
        int e = i >> 7, k = i & 127;
        sWt[k * EMBED + e] = W[i];
    }
    __syncthreads();

    // ---- Phase A: 77 projected rows (b folded into pair rows).
    for (int i = threadIdx.x; i < NPROJ * EMBED; i += 1024) {
        int r = i >> 7, e = i & 127;
        const float* tab; int off, dim; float s = 0.0f;
        if (r < 50)      { tab = level_tab    + r * ATTR;        off = 0;   dim = ATTR; }
        else if (r < 52) { tab = type_tab     + (r - 50) * ATTR; off = 25;  dim = ATTR; }
        else if (r < 54) { tab = feature_tab  + (r - 52) * ATTR; off = 50;  dim = ATTR; }
        else if (r < 57) { tab = exchange_tab + (r - 54) * ATTR; off = 75;  dim = ATTR; }
        else             { tab = pair_tab     + (r - 57) * REM;  off = 100; dim = REM; s = b[e]; }
        #pragma unroll 5
        for (int k = 0; k < dim; k++)
            s += tab[k] * sWt[(off + k) * EMBED + e];
        if (r < 50) sm[r * EMBED + e] = s;
        else        sm[F_TEMP + (r - 50) * EMBED + e] = s;
    }
    __syncthreads();

    // ---- Phase B: 240 combined rows (overwrites W^T overlay).
    {
        const float4* sT4 = reinterpret_cast<const float4*>(sm + F_TEMP);
        float4* sC4 = reinterpret_cast<float4*>(sm) + (F_COMB / 4);
        for (int i = threadIdx.x; i < NCOMB * 32; i += 1024) {
            int c = i >> 5, v = i & 31;
            int p = c % 20, x = (c / 20) % 3, f = (c / 60) % 2, t = c / 120;
            float4 a  = sT4[t * 32 + v];
            float4 bb = sT4[(2 + f) * 32 + v];
            float4 cc = sT4[(4 + x) * 32 + v];
            float4 dd = sT4[(7 + p) * 32 + v];
            float4 s;
            s.x = a.x + bb.x + cc.x + dd.x;
            s.y = a.y + bb.y + cc.y + dd.y;
            s.z = a.z + bb.z + cc.z + dd.z;
            s.w = a.w + bb.w + cc.w + dd.w;
            sC4[c * 32 + v] = s;
        }
    }
    __syncthreads();

    // ---- Phase C: stream with software-pipelined index loads.
    const int lane   = threadIdx.x & 31;
    const int warp   = (blockIdx.x * 1024 + threadIdx.x) >> 5;
    const int nwarps = (gridDim.x * 1024) >> 5;
    const float4* sL4 = reinterpret_cast<const float4*>(sm);
    const float4* sC4 = reinterpret_cast<const float4*>(sm) + (F_COMB / 4);

    const int stride = nwarps * 4;
    int r = warp * 4;

    int4 L, T, F, X, P;
    bool have = (r + 3 < n);
    if (have) {
        L = *reinterpret_cast<const int4*>(level_idx + r);
        T = *reinterpret_cast<const int4*>(type_idx + r);
        F = *reinterpret_cast<const int4*>(feature_idx + r);
        X = *reinterpret_cast<const int4*>(exchange_idx + r);
        P = *reinterpret_cast<const int4*>(pair_idx + r);
    }

    while (have) {
        // Prefetch next iteration's indices (overlaps DRAM latency with this iter's work)
        const int rn = r + stride;
        const bool haven = (rn + 3 < n);
        int4 Ln, Tn, Fn, Xn, Pn;
        if (haven) {
            Ln = *reinterpret_cast<const int4*>(level_idx + rn);
            Tn = *reinterpret_cast<const int4*>(type_idx + rn);
            Fn = *reinterpret_cast<const int4*>(feature_idx + rn);
            Xn = *reinterpret_cast<const int4*>(exchange_idx + rn);
            Pn = *reinterpret_cast<const int4*>(pair_idx + rn);
        }

        int l[4] = {L.x, L.y, L.z, L.w};
        int t[4] = {T.x, T.y, T.z, T.w};
        int f[4] = {F.x, F.y, F.z, F.w};
        int x[4] = {X.x, X.y, X.z, X.w};
        int p[4] = {P.x, P.y, P.z, P.w};

        #pragma unroll
        for (int k = 0; k < 4; k++) {
            int c = ((t[k] * 2 + f[k]) * 3 + x[k]) * 20 + p[k];
            float4 a = sL4[l[k] * 32 + lane];
            float4 q = sC4[c * 32 + lane];
            float4 s;
            s.x = a.x + q.x; s.y = a.y + q.y; s.z = a.z + q.z; s.w = a.w + q.w;
            __stcs(out + (size_t)(r + k) * 32 + lane, s);
        }

        r = rn;
        if (!haven) break;
        L = Ln; T = Tn; F = Fn; X = Xn; P = Pn;
    }

    // tail (handles r..n-1 for the boundary warp)
    for (; r < n; r++) {
        int c = ((type_idx[r] * 2 + feature_idx[r]) * 3 + exchange_idx[r]) * 20 + pair_idx[r];
        float4 a = sL4[level_idx[r] * 32 + lane];
        float4 q = sC4[c * 32 + lane];
        float4 s;
        s.x = a.x + q.x; s.y = a.y + q.y; s.z = a.z + q.z; s.w = a.w + q.w;
        out[(size_t)r * 32 + lane] = s;
    }
}

extern "C" void kernel_launch(void* const* d_in, const int* in_sizes, int n_in,
                              void* d_out, int out_size) {
    const float* level_tab    = (const float*)d_in[0];
    const float* type_tab     = (const float*)d_in[1];
    const float* feature_tab  = (const float*)d_in[2];
    const float* exchange_tab = (const float*)d_in[3];
    const float* pair_tab     = (const float*)d_in[4];
    const float* W            = (const float*)d_in[5];
    const float* b            = (const float*)d_in[6];
    const int* level_idx      = (const int*)d_in[7];
    const int* type_idx       = (const int*)d_in[8];
    const int* feature_idx    = (const int*)d_in[9];
    const int* exchange_idx   = (const int*)d_in[10];
    const int* pair_idx       = (const int*)d_in[11];

    int n = in_sizes[7];   // N rows

    int sm_count = 148;
    cudaDeviceGetAttribute(&sm_count, cudaDevAttrMultiProcessorCount, 0);

    cudaFuncSetAttribute(fused_embed_kernel,
                         cudaFuncAttributeMaxDynamicSharedMemorySize, SMEM_BYTES);

    // One resident wave: 1 block/SM (162 KB smem), 1024 threads.
    fused_embed_kernel<<<sm_count, 1024, SMEM_BYTES>>>(
        level_tab, type_tab, feature_tab, exchange_tab, pair_tab, W, b,
        level_idx, type_idx, feature_idx, exchange_idx, pair_idx,
        (float4*)d_out, n);
}